// round 5
// baseline (speedup 1.0000x reference)
#include <cuda_runtime.h>
#include <math.h>

#define B4 4
#define NPT 4096
#define CH 64
#define KNN 16
#define NPTS (B4*NPT)          // 16384
#define NBST 20                // padded row stride for [64][16] smem tiles

// ---------------- scratch (device globals; no allocation) ----------------
__device__ float g_f1T[B4*NPT*CH];
__device__ float g_f2T[B4*NPT*CH];
__device__ float g_x1T[B4*NPT*3];
__device__ float g_x2T[B4*NPT*3];
__device__ float g_p2nT[B4*NPT*CH];
__device__ int   g_idx1[B4*NPT*KNN];
__device__ int   g_idx2[B4*NPT*KNN];
__device__ float g_wv1T[131*64];
__device__ float g_wk1T[64*64];
__device__ float g_wm1T[64*16];
__device__ float g_WmqT[64*16];
__device__ float g_wp1T[5*64];
__device__ float g_wq2T[64*64];
__device__ float g_wk2T[64*64];
__device__ float g_wv2T[64*64];
__device__ float g_wp2T[4*64];

// ---------------- weight prep: transposes + fused mlp1@q1 ----------------
__global__ void prep_weights(const float* __restrict__ wq1, const float* __restrict__ wk1,
                             const float* __restrict__ wv1, const float* __restrict__ wm1,
                             const float* __restrict__ wp1, const float* __restrict__ wq2,
                             const float* __restrict__ wk2, const float* __restrict__ wv2,
                             const float* __restrict__ wp2)
{
    int t = threadIdx.x;
    for (int i = t; i < 131*64; i += 256) { int o = i/131, c = i%131; g_wv1T[c*64+o] = wv1[i]; }
    for (int i = t; i < 64*64; i += 256) {
        int o = i/64, c = i%64;
        g_wk1T[c*64+o] = wk1[i];
        g_wq2T[c*64+o] = wq2[i];
        g_wk2T[c*64+o] = wk2[i];
        g_wv2T[c*64+o] = wv2[i];
    }
    for (int i = t; i < 16*64; i += 256) { int j = i/64, o = i%64; g_wm1T[o*16+j] = wm1[i]; }
    for (int i = t; i < 64*5;  i += 256) { int o = i/5,  r = i%5;  g_wp1T[r*64+o] = wp1[i]; }
    for (int i = t; i < 64*4;  i += 256) { int o = i/4,  r = i%4;  g_wp2T[r*64+o] = wp2[i]; }
    // WmqT[c*16+j] = sum_o wm1[j][o] * wq1[o][c]
    for (int i = t; i < 64*16; i += 256) {
        int c = i/16, j = i%16;
        float s = 0.f;
        for (int o = 0; o < 64; o++) s += wm1[j*64+o] * wq1[o*64+c];
        g_WmqT[c*16+j] = s;
    }
}

// ---------------- transposes ----------------
__global__ void transpose_feat(const float* __restrict__ in, int which)
{
    __shared__ float tile[64][65];
    float* out = which ? g_f2T : g_f1T;
    int b = blockIdx.y, n0 = blockIdx.x * 64;
    int tx = threadIdx.x, ty = threadIdx.y;
    for (int c = ty; c < 64; c += 8)
        tile[c][tx] = in[(b*64 + c)*NPT + n0 + tx];
    __syncthreads();
    for (int nn = ty; nn < 64; nn += 8)
        out[(b*NPT + n0 + nn)*64 + tx] = tile[tx][nn];
}

__global__ void transpose_xyz(const float* __restrict__ in, int which)
{
    float* out = which ? g_x2T : g_x1T;
    int i = blockIdx.x * blockDim.x + threadIdx.x;
    if (i < B4*NPT) {
        int b = i >> 12, n = i & (NPT-1);
        out[i*3+0] = in[b*3*NPT + n];
        out[i*3+1] = in[b*3*NPT + NPT + n];
        out[i*3+2] = in[b*3*NPT + 2*NPT + n];
    }
}

// ---------------- brute-force KNN: 4 threads/query ----------------
// Full fp32 distances: cross via FMA chain (matches SGEMM/XLA lowering),
// q2/i2 elementwise non-fused, combine rn(rn(q2+i2) - 2*cross).
// Tie-breaking is strict lexicographic (value, index) everywhere to match
// jax.lax.top_k's lower-index-first semantics on equal fp32 distances.
__global__ __launch_bounds__(256) void knn_kernel(const float* __restrict__ qxyz,
                                                  const float* __restrict__ cxyz, int which)
{
    extern __shared__ float sm[];
    float* sx = sm;
    float* sy = sm + NPT;
    float* sz = sm + 2*NPT;
    float* s2 = sm + 3*NPT;
    int* out = which ? g_idx2 : g_idx1;
    int b = blockIdx.y;
    const float* cb = cxyz + b*3*NPT;
    int tid = threadIdx.x;
    for (int i = tid; i < NPT; i += 256) {
        float x = cb[i], y = cb[NPT+i], z = cb[2*NPT+i];
        sx[i] = x; sy[i] = y; sz[i] = z;
        s2[i] = __fadd_rn(__fadd_rn(__fmul_rn(x,x), __fmul_rn(y,y)), __fmul_rn(z,z));
    }
    __syncthreads();

    int ql = tid >> 2, part = tid & 3;
    int n = blockIdx.x * 64 + ql;
    const float* qb = qxyz + b*3*NPT;
    float qx = qb[n], qy = qb[NPT+n], qz = qb[2*NPT+n];
    float q2 = __fadd_rn(__fadd_rn(__fmul_rn(qx,qx), __fmul_rn(qy,qy)), __fmul_rn(qz,qz));

    float bd[16]; int bi[16];
#pragma unroll
    for (int t = 0; t < 16; t++) { bd[t] = 3.0e38f; bi[t] = 0x7fffffff; }
    float worst = 3.0e38f; int wpos = 0;

    int i0 = part * 1024;
    for (int i = i0; i < i0 + 1024; i++) {
        float cross = __fmaf_rn(qz, sz[i], __fmaf_rn(qy, sy[i], __fmul_rn(qx, sx[i])));
        float d = __fsub_rn(__fadd_rn(q2, s2[i]), __fmul_rn(2.0f, cross));
        // strict < : on d == worst keep existing (its index is lower — ascending scan)
        if (d < worst) {
#pragma unroll
            for (int t = 0; t < 16; t++) if (t == wpos) { bd[t] = d; bi[t] = i; }
            // recompute worst slot: max value; among equal maxima evict the LARGER index
            worst = bd[0]; wpos = 0;
            int widx = bi[0];
#pragma unroll
            for (int t = 1; t < 16; t++)
                if (bd[t] > worst || (bd[t] == worst && bi[t] > widx)) {
                    worst = bd[t]; wpos = t; widx = bi[t];
                }
        }
    }

    // merge 4 partial top-16 lists via 16 rounds of 4-lane min-extraction,
    // ties broken toward smaller index everywhere (top_k semantics)
    for (int r = 0; r < 16; r++) {
        float mv = bd[0]; int mi = bi[0]; int mp = 0;
#pragma unroll
        for (int t = 1; t < 16; t++)
            if (bd[t] < mv || (bd[t] == mv && bi[t] < mi)) { mv = bd[t]; mi = bi[t]; mp = t; }
        float gv = mv; int gi = mi;
        float ov = __shfl_xor_sync(0xffffffffu, gv, 1);
        int   oi = __shfl_xor_sync(0xffffffffu, gi, 1);
        if (ov < gv || (ov == gv && oi < gi)) { gv = ov; gi = oi; }
        ov = __shfl_xor_sync(0xffffffffu, gv, 2);
        oi = __shfl_xor_sync(0xffffffffu, gi, 2);
        if (ov < gv || (ov == gv && oi < gi)) { gv = ov; gi = oi; }
        if (gv == mv && gi == mi) {
#pragma unroll
            for (int t = 0; t < 16; t++) if (t == mp) { bd[t] = 3.0e38f; bi[t] = 0x7fffffff; }
        }
        if (part == 0) out[(b*NPT + n)*16 + r] = gi;
    }
}

// 16-wide fused accumulate from a float4-aligned smem row.
// NOTE: macro params named to avoid colliding with float4 member tokens (.x/.y/.z/.w).
#define ACC16(Vc, Wt, Bp) do {                                           \
    const float4 a0 = ((const float4*)(Bp))[0];                          \
    const float4 a1 = ((const float4*)(Bp))[1];                          \
    const float4 a2 = ((const float4*)(Bp))[2];                          \
    const float4 a3 = ((const float4*)(Bp))[3];                          \
    Vc[0]  += (Wt)*a0.x; Vc[1]  += (Wt)*a0.y; Vc[2]  += (Wt)*a0.z; Vc[3]  += (Wt)*a0.w; \
    Vc[4]  += (Wt)*a1.x; Vc[5]  += (Wt)*a1.y; Vc[6]  += (Wt)*a1.z; Vc[7]  += (Wt)*a1.w; \
    Vc[8]  += (Wt)*a2.x; Vc[9]  += (Wt)*a2.y; Vc[10] += (Wt)*a2.z; Vc[11] += (Wt)*a2.w; \
    Vc[12] += (Wt)*a3.x; Vc[13] += (Wt)*a3.y; Vc[14] += (Wt)*a3.z; Vc[15] += (Wt)*a3.w; \
} while (0)

#define ST16(Bp, Vc, Ad) do {                                            \
    ((float4*)(Bp))[0] = make_float4(Vc[0]+Ad[0],  Vc[1]+Ad[1],  Vc[2]+Ad[2],  Vc[3]+Ad[3]);   \
    ((float4*)(Bp))[1] = make_float4(Vc[4]+Ad[4],  Vc[5]+Ad[5],  Vc[6]+Ad[6],  Vc[7]+Ad[7]);   \
    ((float4*)(Bp))[2] = make_float4(Vc[8]+Ad[8],  Vc[9]+Ad[9],  Vc[10]+Ad[10],Vc[11]+Ad[11]); \
    ((float4*)(Bp))[3] = make_float4(Vc[12]+Ad[12],Vc[13]+Ad[13],Vc[14]+Ad[14],Vc[15]+Ad[15]); \
} while (0)

// ---------------- group1 ----------------
// smem: weights 14928 floats + 4 groups * 2752 floats = 25936 floats = 103744 B
#define G1_SMEM (25936*4)
__global__ __launch_bounds__(256, 2) void group1_kernel(const float* __restrict__ wm2,
                                                        const float* __restrict__ bpos1,
                                                        int groups_total, int iters)
{
    extern __shared__ float sm[];
    float* s_wv1T = sm;                 // 8384
    float* s_wk1T = s_wv1T + 8384;      // 4096
    float* s_wm1T = s_wk1T + 4096;      // 1024
    float* s_WmqT = s_wm1T + 1024;      // 1024
    float* s_wp1T = s_WmqT + 1024;      // 320
    float* s_wm2  = s_wp1T + 320;       // 16
    float* s_b1   = s_wm2  + 16;        // 64
    float* s_grp0 = s_b1   + 64;

    int tid = threadIdx.x;
    for (int i = tid; i < 8384; i += 256) s_wv1T[i] = g_wv1T[i];
    for (int i = tid; i < 4096; i += 256) s_wk1T[i] = g_wk1T[i];
    for (int i = tid; i < 1024; i += 256) { s_wm1T[i] = g_wm1T[i]; s_WmqT[i] = g_WmqT[i]; }
    for (int i = tid; i < 320;  i += 256) s_wp1T[i] = g_wp1T[i];
    if (tid < 16) s_wm2[tid] = wm2[tid];
    if (tid < 64) s_b1[tid] = bpos1[tid];

    const int GSZ = 2752;
    int g = tid >> 6, o = tid & 63;
    float* snb  = s_grp0 + g*GSZ;       // [64][20], later reused for k
    float* svpe = snb  + 64*NBST;       // [64][20]
    float* spts = svpe + 64*NBST;       // 64
    float* spos = spts + 64;            // [5][16]
    float* smq  = spos + 80;            // 16
    float* slog = smq  + 16;            // 16
    int*   sidx = (int*)(slog + 16);    // 16
    int gg = blockIdx.x * 4 + g;
    __syncthreads();

    for (int it = 0; it < iters; it++) {
        int p = gg + it * groups_total;
        bool active = p < NPTS;
        int b = p >> 12;

        if (active) {
            if (o < 16) sidx[o] = g_idx1[(p<<4) + o];
            spts[o] = g_f1T[(p<<6) + o];
        }
        __syncthreads();
        if (active) {
#pragma unroll
            for (int s = 0; s < 16; s++) {
                int id = sidx[s];
                snb[o*NBST + s] = g_f2T[(((b<<12) + id)<<6) + o];
            }
        }
        __syncthreads();

        float vbase = 0.f;
#pragma unroll 8
        for (int c = 0; c < 64; c++) vbase += s_wv1T[c*64+o] * spts[c];

        if (active && o < 16) {
            int s = o; int id = sidx[s];
            const float* q3 = g_x1T + p*3;
            const float* c3 = g_x2T + ((b<<12) + id)*3;
            float dx = q3[0]-c3[0], dy = q3[1]-c3[1], dz = q3[2]-c3[2];
            float fn2 = 0.f;
#pragma unroll 8
            for (int c = 0; c < 64; c++) { float t = spts[c] - snb[c*NBST+s]; fn2 += t*t; }
            spos[0*16+s] = sqrtf(fn2);
            spos[1*16+s] = sqrtf(dx*dx + dy*dy + dz*dz);
            spos[2*16+s] = dx; spos[3*16+s] = dy; spos[4*16+s] = dz;
            float mq = 0.f;
#pragma unroll 8
            for (int c = 0; c < 64; c++) mq += s_WmqT[c*16+s] * spts[c];
            smq[s] = mq;
        }
        __syncthreads();

        // v[o][s]
        float v[16];
#pragma unroll
        for (int s = 0; s < 16; s++) v[s] = vbase;
#pragma unroll
        for (int j = 0; j < 3; j++) {
            float wj = s_wv1T[(128+j)*64 + o];
#pragma unroll
            for (int s = 0; s < 16; s++) v[s] += wj * spos[(2+j)*16 + s];
        }
#pragma unroll 4
        for (int c = 0; c < 64; c++) {
            float wc = s_wv1T[(64+c)*64 + o];
            ACC16(v, wc, snb + c*NBST);
        }
        // pos_enc
        float pe[16];
        float bb = s_b1[o];
#pragma unroll
        for (int s = 0; s < 16; s++) pe[s] = bb;
#pragma unroll
        for (int r = 0; r < 5; r++) {
            float wr = s_wp1T[r*64 + o];
#pragma unroll
            for (int s = 0; s < 16; s++) pe[s] += wr * spos[r*16 + s];
        }
        ST16(svpe + o*NBST, v, pe);
        __syncthreads();

        // k[o][s]
        float kk[16];
#pragma unroll
        for (int s = 0; s < 16; s++) kk[s] = 0.f;
#pragma unroll 4
        for (int c = 0; c < 64; c++) {
            float wc = s_wk1T[c*64 + o];
            ACC16(kk, wc, svpe + c*NBST);
        }
        {
            float z[16];
#pragma unroll
            for (int s = 0; s < 16; s++) z[s] = 0.f;
            ST16(snb + o*NBST, kk, z);     // snb reused as k buffer
        }
        __syncthreads();

        // attn logits: h = relu(mq - wm1 @ k), logit = wm2 @ h
        {
            int j = o & 15, sb = o >> 4;
#pragma unroll
            for (int ss = 0; ss < 4; ss++) {
                int s = sb*4 + ss;
                float h = smq[j];
#pragma unroll 8
                for (int op = 0; op < 64; op++) h -= s_wm1T[op*16+j] * snb[op*NBST+s];
                h = fmaxf(h, 0.f);
                float part = s_wm2[j] * h;
                part += __shfl_xor_sync(0xffffffffu, part, 1);
                part += __shfl_xor_sync(0xffffffffu, part, 2);
                part += __shfl_xor_sync(0xffffffffu, part, 4);
                part += __shfl_xor_sync(0xffffffffu, part, 8);
                if (j == 0) slog[s] = part;
            }
        }
        __syncthreads();

        // softmax + weighted sum + leaky
        float mx = -3.0e38f;
#pragma unroll
        for (int s = 0; s < 16; s++) mx = fmaxf(mx, slog[s]);
        float sum = 0.f, outv = 0.f;
#pragma unroll
        for (int s = 0; s < 16; s++) {
            float e = __expf(slog[s] - mx);
            sum += e; outv += e * v[s];
        }
        outv /= sum;
        outv = (outv >= 0.f) ? outv : 0.1f*outv;
        if (active) g_p2nT[(p<<6) + o] = outv;
        __syncthreads();
    }
}

// ---------------- group2 ----------------
// smem: weights 12608 floats + 4 groups * 2752 = 23616 floats = 94464 B
#define G2_SMEM (23616*4)
__global__ __launch_bounds__(256, 2) void group2_kernel(const float* __restrict__ bpos2,
                                                        float* __restrict__ outp,
                                                        int groups_total, int iters)
{
    extern __shared__ float sm[];
    float* s_wq2T = sm;                 // 4096
    float* s_wk2T = s_wq2T + 4096;      // 4096
    float* s_wv2T = s_wk2T + 4096;      // 4096
    float* s_wp2T = s_wv2T + 4096;      // 256
    float* s_b2   = s_wp2T + 256;       // 64
    float* s_grp0 = s_b2   + 64;

    int tid = threadIdx.x;
    for (int i = tid; i < 4096; i += 256) {
        s_wq2T[i] = g_wq2T[i]; s_wk2T[i] = g_wk2T[i]; s_wv2T[i] = g_wv2T[i];
    }
    for (int i = tid; i < 256; i += 256) s_wp2T[i] = g_wp2T[i];
    if (tid < 64) s_b2[tid] = bpos2[tid];

    const int GSZ = 2752;
    int g = tid >> 6, o = tid & 63;
    float* snb  = s_grp0 + g*GSZ;       // [64][20]
    float* stmp = snb  + 64*NBST;       // [64][20]
    float* spts = stmp + 64*NBST;       // 64
    float* spos = spts + 64;            // [4][16]
    float* slog = spos + 64;            // 16 (scratch)
    float* sred = slog + 16;            // 32
    int*   sidx = (int*)(sred + 32);    // 16
    int gg = blockIdx.x * 4 + g;
    __syncthreads();

    for (int it = 0; it < iters; it++) {
        int p = gg + it * groups_total;
        bool active = p < NPTS;
        int b = p >> 12, n = p & (NPT-1);

        if (active) {
            if (o < 16) sidx[o] = g_idx2[(p<<4) + o];
            spts[o] = g_p2nT[(p<<6) + o];
        }
        __syncthreads();
        if (active) {
#pragma unroll
            for (int s = 0; s < 16; s++) {
                int id = sidx[s];
                snb[o*NBST + s] = g_p2nT[(((b<<12) + id)<<6) + o];
            }
        }
        __syncthreads();

        float q = 0.f;
#pragma unroll 8
        for (int c = 0; c < 64; c++) q += s_wq2T[c*64+o] * spts[c];
        q *= 0.125f;   // 64^-0.5

        if (active && o < 16) {
            int s = o; int id = sidx[s];
            const float* q3 = g_x1T + p*3;
            const float* c3 = g_x1T + ((b<<12) + id)*3;
            float dx = q3[0]-c3[0], dy = q3[1]-c3[1], dz = q3[2]-c3[2];
            spos[0*16+s] = dx; spos[1*16+s] = dy; spos[2*16+s] = dz;
            spos[3*16+s] = sqrtf(dx*dx + dy*dy + dz*dz);
        }
        __syncthreads();

        // tmp = nb + pos_enc
        float pe[16];
        float bb = s_b2[o];
#pragma unroll
        for (int s = 0; s < 16; s++) pe[s] = bb;
#pragma unroll
        for (int r = 0; r < 4; r++) {
            float wr = s_wp2T[r*64 + o];
#pragma unroll
            for (int s = 0; s < 16; s++) pe[s] += wr * spos[r*16 + s];
        }
        {
            float nbv[16];
            const float4* rp = (const float4*)(snb + o*NBST);
            float4 a0 = rp[0], a1 = rp[1], a2 = rp[2], a3 = rp[3];
            nbv[0]=a0.x; nbv[1]=a0.y; nbv[2]=a0.z; nbv[3]=a0.w;
            nbv[4]=a1.x; nbv[5]=a1.y; nbv[6]=a1.z; nbv[7]=a1.w;
            nbv[8]=a2.x; nbv[9]=a2.y; nbv[10]=a2.z; nbv[11]=a2.w;
            nbv[12]=a3.x; nbv[13]=a3.y; nbv[14]=a3.z; nbv[15]=a3.w;
            ST16(stmp + o*NBST, nbv, pe);
        }
        __syncthreads();

        // k = wk2 @ tmp ; v = wv2 @ nb
        float kk[16], vv[16];
#pragma unroll
        for (int s = 0; s < 16; s++) { kk[s] = 0.f; vv[s] = 0.f; }
#pragma unroll 2
        for (int c = 0; c < 64; c++) {
            float wk = s_wk2T[c*64 + o];
            float wv = s_wv2T[c*64 + o];
            ACC16(kk, wk, stmp + c*NBST);
            ACC16(vv, wv, snb + c*NBST);
        }

        // logits[s] = sum_o q[o]*k[o][s] : warp reduce then cross-warp via smem
#pragma unroll
        for (int s = 0; s < 16; s++) {
            float x = q * kk[s];
            x += __shfl_xor_sync(0xffffffffu, x, 16);
            x += __shfl_xor_sync(0xffffffffu, x, 8);
            x += __shfl_xor_sync(0xffffffffu, x, 4);
            x += __shfl_xor_sync(0xffffffffu, x, 2);
            x += __shfl_xor_sync(0xffffffffu, x, 1);
            kk[s] = x;
        }
        if ((o & 31) == 0) {
#pragma unroll
            for (int s = 0; s < 16; s++) sred[(o>>5)*16 + s] = kk[s];
        }
        __syncthreads();

        float lg[16];
#pragma unroll
        for (int s = 0; s < 16; s++) lg[s] = sred[s] + sred[16+s];
        float mx = -3.0e38f;
#pragma unroll
        for (int s = 0; s < 16; s++) mx = fmaxf(mx, lg[s]);
        float sum = 0.f, outv = 0.f;
#pragma unroll
        for (int s = 0; s < 16; s++) {
            float e = __expf(lg[s] - mx);
            sum += e; outv += e * vv[s];
        }
        outv /= sum;
        outv = (outv >= 0.f) ? outv : 0.1f*outv;
        if (active) outp[(b*64 + o)*NPT + n] = outv;
        __syncthreads();
    }
}

// ---------------- launch ----------------
extern "C" void kernel_launch(void* const* d_in, const int* in_sizes, int n_in,
                              void* d_out, int out_size)
{
    const float* xyz1  = (const float*)d_in[0];
    const float* feat1 = (const float*)d_in[1];
    const float* xyz2  = (const float*)d_in[2];
    const float* feat2 = (const float*)d_in[3];
    const float* wq1   = (const float*)d_in[4];
    const float* wk1   = (const float*)d_in[5];
    const float* wv1   = (const float*)d_in[6];
    const float* wm1   = (const float*)d_in[7];
    const float* wm2   = (const float*)d_in[8];
    const float* wp1   = (const float*)d_in[9];
    const float* b1    = (const float*)d_in[10];
    const float* wq2   = (const float*)d_in[11];
    const float* wk2   = (const float*)d_in[12];
    const float* wv2   = (const float*)d_in[13];
    const float* wp2   = (const float*)d_in[14];
    const float* b2    = (const float*)d_in[15];
    float* out = (float*)d_out;

    cudaFuncSetAttribute(knn_kernel,    cudaFuncAttributeMaxDynamicSharedMemorySize, 4*NPT*4);
    cudaFuncSetAttribute(group1_kernel, cudaFuncAttributeMaxDynamicSharedMemorySize, G1_SMEM);
    cudaFuncSetAttribute(group2_kernel, cudaFuncAttributeMaxDynamicSharedMemorySize, G2_SMEM);

    prep_weights<<<1, 256>>>(wq1, wk1, wv1, wm1, wp1, wq2, wk2, wv2, wp2);
    transpose_feat<<<dim3(64, B4), dim3(64, 8)>>>(feat1, 0);
    transpose_feat<<<dim3(64, B4), dim3(64, 8)>>>(feat2, 1);
    transpose_xyz<<<(B4*NPT + 255)/256, 256>>>(xyz1, 0);
    transpose_xyz<<<(B4*NPT + 255)/256, 256>>>(xyz2, 1);
    knn_kernel<<<dim3(64, B4), 256, 4*NPT*4>>>(xyz1, xyz2, 0);
    knn_kernel<<<dim3(64, B4), 256, 4*NPT*4>>>(xyz1, xyz1, 1);

    const int GRID = 296;                 // 2 blocks/SM on 148 SMs
    const int GROUPS = GRID * 4;          // 1184 point-groups
    const int ITERS = (NPTS + GROUPS - 1) / GROUPS;   // 14
    group1_kernel<<<GRID, 256, G1_SMEM>>>(wm2, b1, GROUPS, ITERS);
    group2_kernel<<<GRID, 256, G2_SMEM>>>(b2, out, GROUPS, ITERS);
}